// round 1
// baseline (speedup 1.0000x reference)
#include <cuda_runtime.h>
#include <cuda_bf16.h>
#include <math.h>

#define NN 64
#define BATCH 4096
#define EPS_PEN 0.1f

__device__ float g_pen[BATCH];

// Block-wide (64-thread, 2-warp) sum reduction.
__device__ __forceinline__ float block_reduce64(float v, volatile float* red) {
    #pragma unroll
    for (int o = 16; o > 0; o >>= 1)
        v += __shfl_xor_sync(0xffffffffu, v, o);
    if ((threadIdx.x & 31) == 0) red[threadIdx.x >> 5] = v;
    __syncthreads();
    float r = red[0] + red[1];
    __syncthreads();
    return r;
}

__global__ void __launch_bounds__(64)
spectral_eig_kernel(const float* __restrict__ logits) {
    __shared__ float M[NN][NN + 1];   // padded: column access conflict-free
    __shared__ float u[NN];
    __shared__ float w[NN];
    __shared__ float dd[NN];
    __shared__ float ee2[NN];
    __shared__ float red[2];

    const int tid = threadIdx.x;
    const int b = blockIdx.x;
    const float* src = logits + (size_t)b * NN * NN;

    // ---- Load + sigmoid (coalesced) ----
    for (int idx = tid; idx < NN * NN; idx += 64) {
        float x = src[idx];
        float s = 1.0f / (1.0f + __expf(-x));
        M[idx >> 6][idx & 63] = s;
    }
    __syncthreads();

    // ---- degree of row tid (A includes diagonal) ----
    float deg = 0.0f;
    #pragma unroll 8
    for (int j = 0; j < NN; j++) deg += M[tid][j];
    float aii = M[tid][tid];
    __syncthreads();   // all reads of A done before overwrite

    // ---- Build symmetrized Laplacian M = (L + L^T)/2 in place ----
    // off-diagonal: -(A_ij + A_ji)/2 ; diagonal: deg_i - A_ii
    for (int j = tid + 1; j < NN; j++) {
        float v = -0.5f * (M[tid][j] + M[j][tid]);
        M[tid][j] = v;
        M[j][tid] = v;
    }
    M[tid][tid] = deg - aii;
    __syncthreads();

    // ---- Householder tridiagonalization ----
    for (int k = 0; k < NN - 2; k++) {
        // sigma = sum_{i>k} M[i][k]^2
        float xi = (tid > k) ? M[tid][k] : 0.0f;
        float sigma = block_reduce64(xi * xi, red);

        float x1 = M[k + 1][k];                 // uniform read (broadcast)
        float nrm = sqrtf(sigma);
        float alpha = (x1 >= 0.0f) ? -nrm : nrm;
        if (tid == 0) ee2[k] = sigma;           // e_k^2 = alpha^2 = sigma

        float vnorm2 = 2.0f * (sigma - x1 * alpha);
        float invv = 2.0f / fmaxf(vnorm2, 1e-30f);   // beta

        float vi = (tid > k) ? M[tid][k] : 0.0f;
        if (tid == k + 1) vi -= alpha;
        u[tid] = vi;
        __syncthreads();

        // p_i = beta * sum_j M[i][j] u[j]   (trailing block only)
        float pi = 0.0f;
        if (tid > k) {
            #pragma unroll 4
            for (int j = k + 1; j < NN; j++) pi += M[tid][j] * u[j];
            pi *= invv;
        }

        // K = (beta/2) v^T p ; w = p - K v
        float s = block_reduce64(u[tid] * pi, red);
        float K = 0.5f * invv * s;
        w[tid] = pi - K * u[tid];
        __syncthreads();

        // rank-2 update: M -= v w^T + w v^T on trailing block
        if (tid > k) {
            float vloc = u[tid];
            float wloc = w[tid];
            #pragma unroll 4
            for (int j = k + 1; j < NN; j++)
                M[tid][j] -= vloc * w[j] + wloc * u[j];
        }
        __syncthreads();
    }

    // ---- Extract tridiagonal ----
    dd[tid] = M[tid][tid];
    if (tid == 0) {
        float t = M[NN - 1][NN - 2];
        ee2[NN - 2] = t * t;
        ee2[NN - 1] = 0.0f;
    }
    __syncthreads();

    // ---- Warp-0 multisection bisection for lambda_2 (Sturm counts) ----
    if (tid < 32) {
        // Gershgorin bounds of tridiagonal
        float gl = 1e30f, gu = -1e30f;
        for (int i = tid; i < NN; i += 32) {
            float ei  = sqrtf(ee2[i]);
            float eim = (i > 0) ? sqrtf(ee2[i - 1]) : 0.0f;
            float r = ei + eim;
            gl = fminf(gl, dd[i] - r);
            gu = fmaxf(gu, dd[i] + r);
        }
        #pragma unroll
        for (int o = 16; o > 0; o >>= 1) {
            gl = fminf(gl, __shfl_xor_sync(0xffffffffu, gl, o));
            gu = fmaxf(gu, __shfl_xor_sync(0xffffffffu, gu, o));
        }

        float lo = gl, hi = gu;
        // invariant: count(lo) < 2 <= count(hi). 6 rounds of 33-section: /1.3e9
        #pragma unroll 1
        for (int round = 0; round < 6; round++) {
            float stepw = (hi - lo) * (1.0f / 33.0f);
            float x = lo + stepw * (float)(tid + 1);
            // negcount: # eigenvalues < x
            float q = dd[0] - x;
            int c = (q < 0.0f);
            #pragma unroll 1
            for (int i = 1; i < NN; i++) {
                float den = q;
                if (fabsf(den) < 1e-30f) den = -1e-30f;
                q = dd[i] - x - ee2[i - 1] / den;
                c += (q < 0.0f);
            }
            unsigned bal = __ballot_sync(0xffffffffu, c >= 2);
            if (bal == 0u) {
                lo += stepw * 32.0f;
            } else {
                int t = __ffs(bal) - 1;
                hi = lo + stepw * (float)(t + 1);
                lo += stepw * (float)t;
            }
        }
        float lambda2 = 0.5f * (lo + hi);
        if (tid == 0) g_pen[b] = fmaxf(0.0f, EPS_PEN - lambda2);
    }
}

__global__ void __launch_bounds__(256)
mean_kernel(float* __restrict__ out) {
    __shared__ float red[8];
    float s = 0.0f;
    for (int i = threadIdx.x; i < BATCH; i += 256) s += g_pen[i];
    #pragma unroll
    for (int o = 16; o > 0; o >>= 1)
        s += __shfl_xor_sync(0xffffffffu, s, o);
    if ((threadIdx.x & 31) == 0) red[threadIdx.x >> 5] = s;
    __syncthreads();
    if (threadIdx.x == 0) {
        float t = 0.0f;
        #pragma unroll
        for (int i = 0; i < 8; i++) t += red[i];
        out[0] = t * (1.0f / (float)BATCH);
    }
}

extern "C" void kernel_launch(void* const* d_in, const int* in_sizes, int n_in,
                              void* d_out, int out_size) {
    const float* logits = (const float*)d_in[0];   // [4096, 64, 64] float32
    // d_in[1] = node_types (int64) — unused by the reference computation
    float* out = (float*)d_out;

    spectral_eig_kernel<<<BATCH, 64>>>(logits);
    mean_kernel<<<1, 256>>>(out);
}

// round 2
// speedup vs baseline: 44.4301x; 44.4301x over previous
#include <cuda_runtime.h>
#include <cuda_bf16.h>
#include <math.h>

#define NN 64
#define BATCH 4096
#define EPS_PEN 0.1f
#define PEN_SCALE 1099511627776.0   // 2^40 fixed-point for deterministic atomic sum

__device__ unsigned long long g_acc;   // zero-initialized; finalize resets to 0 each call

// Block-wide (64-thread, 2-warp) sum reduction.
__device__ __forceinline__ float block_reduce64(float v, volatile float* red) {
    #pragma unroll
    for (int o = 16; o > 0; o >>= 1)
        v += __shfl_xor_sync(0xffffffffu, v, o);
    if ((threadIdx.x & 31) == 0) red[threadIdx.x >> 5] = v;
    __syncthreads();
    float r = red[0] + red[1];
    __syncthreads();
    return r;
}

__global__ void __launch_bounds__(64)
spectral_kernel(const float* __restrict__ logits) {
    __shared__ float M[NN][NN + 1];   // padded: column access conflict-free
    __shared__ float u[NN];
    __shared__ float w[NN];
    __shared__ float dd[NN];
    __shared__ float ee2[NN];
    __shared__ float red[2];

    const int tid = threadIdx.x;
    const int b = blockIdx.x;
    const float* src = logits + (size_t)b * NN * NN;

    // ================= FAST PATH =================
    // lambda_2(M) >= NN * min_ij w_ij >= NN * sigmoid(min_ij x_ij)
    // (M - w_min*L_K64 is a Laplacian of nonneg weights => PSD).
    // If that bound >= EPS, penalty is exactly relu-clamped to 0: skip eigensolve.
    {
        const float4* src4 = (const float4*)src;
        float xmin = 1e30f;
        #pragma unroll
        for (int i = 0; i < 16; i++) {
            float4 v = src4[tid + 64 * i];
            xmin = fminf(xmin, fminf(fminf(v.x, v.y), fminf(v.z, v.w)));
        }
        #pragma unroll
        for (int o = 16; o > 0; o >>= 1)
            xmin = fminf(xmin, __shfl_xor_sync(0xffffffffu, xmin, o));
        if ((tid & 31) == 0) red[tid >> 5] = xmin;
        __syncthreads();
        xmin = fminf(red[0], red[1]);            // uniform across block

        float bound = (float)NN / (1.0f + expf(-xmin));
        if (bound >= EPS_PEN) return;            // penalty == 0, contributes nothing
        __syncthreads();                          // red[] will be reused below
    }

    // ================= SLOW PATH (certified bound failed) =================
    // ---- Load + sigmoid (coalesced; data is hot in L2 from the min pass) ----
    for (int idx = tid; idx < NN * NN; idx += 64) {
        float x = src[idx];
        float s = 1.0f / (1.0f + expf(-x));
        M[idx >> 6][idx & 63] = s;
    }
    __syncthreads();

    // ---- degree of row tid (A includes diagonal) ----
    float deg = 0.0f;
    #pragma unroll 8
    for (int j = 0; j < NN; j++) deg += M[tid][j];
    float aii = M[tid][tid];
    __syncthreads();

    // ---- Build symmetrized Laplacian (L + L^T)/2 in place ----
    for (int j = tid + 1; j < NN; j++) {
        float v = -0.5f * (M[tid][j] + M[j][tid]);
        M[tid][j] = v;
        M[j][tid] = v;
    }
    M[tid][tid] = deg - aii;
    __syncthreads();

    // ---- Householder tridiagonalization ----
    for (int k = 0; k < NN - 2; k++) {
        float xi = (tid > k) ? M[tid][k] : 0.0f;
        float sigma = block_reduce64(xi * xi, red);

        float x1 = M[k + 1][k];
        float nrm = sqrtf(sigma);
        float alpha = (x1 >= 0.0f) ? -nrm : nrm;
        if (tid == 0) ee2[k] = sigma;

        float vnorm2 = 2.0f * (sigma - x1 * alpha);
        float invv = 2.0f / fmaxf(vnorm2, 1e-30f);

        float vi = (tid > k) ? M[tid][k] : 0.0f;
        if (tid == k + 1) vi -= alpha;
        u[tid] = vi;
        __syncthreads();

        float pi = 0.0f;
        if (tid > k) {
            #pragma unroll 4
            for (int j = k + 1; j < NN; j++) pi += M[tid][j] * u[j];
            pi *= invv;
        }

        float s = block_reduce64(u[tid] * pi, red);
        float K = 0.5f * invv * s;
        w[tid] = pi - K * u[tid];
        __syncthreads();

        if (tid > k) {
            float vloc = u[tid];
            float wloc = w[tid];
            #pragma unroll 4
            for (int j = k + 1; j < NN; j++)
                M[tid][j] -= vloc * w[j] + wloc * u[j];
        }
        __syncthreads();
    }

    // ---- Extract tridiagonal ----
    dd[tid] = M[tid][tid];
    if (tid == 0) {
        float t = M[NN - 1][NN - 2];
        ee2[NN - 2] = t * t;
        ee2[NN - 1] = 0.0f;
    }
    __syncthreads();

    // ---- Warp-0 multisection bisection for lambda_2 ----
    if (tid < 32) {
        float gl = 1e30f, gu = -1e30f;
        for (int i = tid; i < NN; i += 32) {
            float ei  = sqrtf(ee2[i]);
            float eim = (i > 0) ? sqrtf(ee2[i - 1]) : 0.0f;
            float r = ei + eim;
            gl = fminf(gl, dd[i] - r);
            gu = fmaxf(gu, dd[i] + r);
        }
        #pragma unroll
        for (int o = 16; o > 0; o >>= 1) {
            gl = fminf(gl, __shfl_xor_sync(0xffffffffu, gl, o));
            gu = fmaxf(gu, __shfl_xor_sync(0xffffffffu, gu, o));
        }

        float lo = gl, hi = gu;
        #pragma unroll 1
        for (int round = 0; round < 6; round++) {
            float stepw = (hi - lo) * (1.0f / 33.0f);
            float x = lo + stepw * (float)(tid + 1);
            float q = dd[0] - x;
            int c = (q < 0.0f);
            #pragma unroll 1
            for (int i = 1; i < NN; i++) {
                float den = q;
                if (fabsf(den) < 1e-30f) den = -1e-30f;
                q = dd[i] - x - ee2[i - 1] / den;
                c += (q < 0.0f);
            }
            unsigned bal = __ballot_sync(0xffffffffu, c >= 2);
            if (bal == 0u) {
                lo += stepw * 32.0f;
            } else {
                int t = __ffs(bal) - 1;
                hi = lo + stepw * (float)(t + 1);
                lo += stepw * (float)t;
            }
        }
        float lambda2 = 0.5f * (lo + hi);
        if (tid == 0) {
            float pen = fmaxf(0.0f, EPS_PEN - lambda2);
            // fixed-point accumulation: order-independent => deterministic
            unsigned long long q = (unsigned long long)((double)pen * PEN_SCALE);
            atomicAdd(&g_acc, q);
        }
    }
}

__global__ void finalize_kernel(float* __restrict__ out) {
    unsigned long long a = g_acc;
    out[0] = (float)((double)a * (1.0 / PEN_SCALE) * (1.0 / (double)BATCH));
    g_acc = 0ull;   // reset for next graph replay
}

extern "C" void kernel_launch(void* const* d_in, const int* in_sizes, int n_in,
                              void* d_out, int out_size) {
    const float* logits = (const float*)d_in[0];   // [4096, 64, 64] float32
    // d_in[1] = node_types (int64) — unused by the reference computation
    float* out = (float*)d_out;

    spectral_kernel<<<BATCH, 64>>>(logits);
    finalize_kernel<<<1, 1>>>(out);
}